// round 14
// baseline (speedup 1.0000x reference)
#include <cuda_runtime.h>
#include <cuda_bf16.h>
#include <cuda_fp16.h>
#include <cstdint>

#define NMAX 100000
#define EMAX 1600000
#define BCAP 64                 // fixed bucket capacity per node
#define OVFCAP 32768            // overflow edges (deg > BCAP), ~never used

typedef unsigned long long ull;

// ---------------- device scratch (static: no runtime allocation) ------------
__device__ __half2 g_hh[(size_t)NMAX * 64];   // x @ W   [N,128] as half2[N,64]
__device__ float   g_asrc[NMAX * 4];          // per-node att logits * log2(e)
__device__ float   g_adst[NMAX * 4];          // per-node att logits * log2(e)
__device__ int     g_cursor[NMAX];            // per-node degree counter
__device__ int     g_bucket[(size_t)NMAX * BCAP];  // src ids, fixed slots per dst
__device__ int2    g_ovf[OVFCAP];             // (dst, src) overflow edges
__device__ int     g_ovfcnt;
__device__ float   g_colsum[128];
__device__ float   g_colsq[128];
__device__ int     g_is64;                    // edge_index dtype flag

// ---------------- init (+ fused edge dtype detection) -----------------------
__global__ void init_kernel(const int* __restrict__ w, int n) {
    int i = blockIdx.x * blockDim.x + threadIdx.x;
    if (i == 0) {
        int all0 = 1;
        for (int j = 1; j < 64; j += 2) all0 &= (w[j] == 0);
        g_is64 = all0;
        g_ovfcnt = 0;
    }
    if (i < n) g_cursor[i] = 0;
    if (i < 128) { g_colsum[i] = 0.f; g_colsq[i] = 0.f; }
}

// ---------------- GEMM via mma.sync bf16 2-term split, fused logits ---------
#define MMA_BF16(d, a0, a1, a2, a3, b0, b1) \
    asm volatile("mma.sync.aligned.m16n8k16.row.col.f32.bf16.bf16.f32 " \
        "{%0,%1,%2,%3}, {%4,%5,%6,%7}, {%8,%9}, {%0,%1,%2,%3};" \
        : "+f"((d)[0]), "+f"((d)[1]), "+f"((d)[2]), "+f"((d)[3]) \
        : "r"(a0), "r"(a1), "r"(a2), "r"(a3), "r"(b0), "r"(b1))

static constexpr int AST = 136;                       // bf16 row stride (conflict-free)
static constexpr int SZ_TILE = 128 * AST * 2;         // 34816 B per bf16 tile
static constexpr int SM_AHI = 0;
static constexpr int SM_ALO = SM_AHI + SZ_TILE;
static constexpr int SM_BHI = SM_ALO + SZ_TILE;       // Wt [n][k]
static constexpr int SM_BLO = SM_BHI + SZ_TILE;
static constexpr int SM_ATT = SM_BLO + SZ_TILE;       // 256 floats (src|dst)
static constexpr int GEMM_SMEM = SM_ATT + 1024;       // 140288 B
static constexpr float LOG2E = 1.4426950408889634f;

__global__ __launch_bounds__(256, 1) void gemm_mma_kernel(
    const float4* __restrict__ x4, const float* __restrict__ W,
    const float* __restrict__ att_src, const float* __restrict__ att_dst,
    int n)
{
    extern __shared__ char smem[];
    __nv_bfloat16* sAhi = (__nv_bfloat16*)(smem + SM_AHI);
    __nv_bfloat16* sAlo = (__nv_bfloat16*)(smem + SM_ALO);
    __nv_bfloat16* sBhi = (__nv_bfloat16*)(smem + SM_BHI);
    __nv_bfloat16* sBlo = (__nv_bfloat16*)(smem + SM_BLO);
    float* s_att = (float*)(smem + SM_ATT);           // [0:128) src, [128:256) dst

    const int tid = threadIdx.x;
    const int row0 = blockIdx.x * 128;

    if (tid < 128) { s_att[tid] = att_src[tid]; s_att[128 + tid] = att_dst[tid]; }

    for (int i = tid; i < 128 * 128; i += 256) {
        int k = i >> 7, nn = i & 127;
        float w = W[i];
        __nv_bfloat16 hi = __float2bfloat16(w);
        __nv_bfloat16 lo = __float2bfloat16(w - __bfloat162float(hi));
        sBhi[nn * AST + k] = hi;
        sBlo[nn * AST + k] = lo;
    }
    for (int i = tid; i < 128 * 32; i += 256) {
        int r = i >> 5, q = i & 31;
        int grow = row0 + r;
        float4 v = make_float4(0.f, 0.f, 0.f, 0.f);
        if (grow < n) v = x4[(size_t)grow * 32 + q];
        __nv_bfloat162 h0 = __floats2bfloat162_rn(v.x, v.y);
        __nv_bfloat162 h1 = __floats2bfloat162_rn(v.z, v.w);
        __nv_bfloat162 l0 = __floats2bfloat162_rn(v.x - __bfloat162float(h0.x),
                                                  v.y - __bfloat162float(h0.y));
        __nv_bfloat162 l1 = __floats2bfloat162_rn(v.z - __bfloat162float(h1.x),
                                                  v.w - __bfloat162float(h1.y));
        uint32_t base = r * AST + q * 4;
        *(uint32_t*)&sAhi[base]     = *(uint32_t*)&h0;
        *(uint32_t*)&sAhi[base + 2] = *(uint32_t*)&h1;
        *(uint32_t*)&sAlo[base]     = *(uint32_t*)&l0;
        *(uint32_t*)&sAlo[base + 2] = *(uint32_t*)&l1;
    }
    __syncthreads();

    const int lane = tid & 31, warp = tid >> 5;
    const int g = lane >> 2, tig = lane & 3;
    const int mrow = warp * 16;

    float d[16][4];
#pragma unroll
    for (int nt = 0; nt < 16; nt++)
#pragma unroll
        for (int j = 0; j < 4; j++) d[nt][j] = 0.f;

#pragma unroll
    for (int term = 0; term < 3; term++) {
        const __nv_bfloat16* A = (term == 2) ? sAlo : sAhi;
        const __nv_bfloat16* B = (term == 1) ? sBlo : sBhi;
#pragma unroll
        for (int k0 = 0; k0 < 128; k0 += 16) {
            int kc = k0 + tig * 2;
            uint32_t a0 = *(const uint32_t*)&A[(mrow + g) * AST + kc];
            uint32_t a1 = *(const uint32_t*)&A[(mrow + g + 8) * AST + kc];
            uint32_t a2 = *(const uint32_t*)&A[(mrow + g) * AST + kc + 8];
            uint32_t a3 = *(const uint32_t*)&A[(mrow + g + 8) * AST + kc + 8];
#pragma unroll
            for (int nt = 0; nt < 16; nt++) {
                uint32_t b0 = *(const uint32_t*)&B[(nt * 8 + g) * AST + kc];
                uint32_t b1 = *(const uint32_t*)&B[(nt * 8 + g) * AST + kc + 8];
                MMA_BF16(d[nt], a0, a1, a2, a3, b0, b1);
            }
        }
    }

    const int r0 = row0 + mrow + g;
    const int r1 = r0 + 8;
    float ps0[4], pd0[4], ps1[4], pd1[4];
#pragma unroll
    for (int h = 0; h < 4; h++) { ps0[h] = pd0[h] = ps1[h] = pd1[h] = 0.f; }
#pragma unroll
    for (int nt = 0; nt < 16; nt++) {
        int c0 = nt * 8 + tig * 2;
        int h = nt >> 2;
        float a_s0 = s_att[c0], a_s1 = s_att[c0 + 1];
        float a_d0 = s_att[128 + c0], a_d1 = s_att[128 + c0 + 1];
        ps0[h] += d[nt][0] * a_s0 + d[nt][1] * a_s1;
        pd0[h] += d[nt][0] * a_d0 + d[nt][1] * a_d1;
        ps1[h] += d[nt][2] * a_s0 + d[nt][3] * a_s1;
        pd1[h] += d[nt][2] * a_d0 + d[nt][3] * a_d1;
        if (r0 < n) g_hh[(size_t)r0 * 64 + (c0 >> 1)] = __floats2half2_rn(d[nt][0], d[nt][1]);
        if (r1 < n) g_hh[(size_t)r1 * 64 + (c0 >> 1)] = __floats2half2_rn(d[nt][2], d[nt][3]);
    }
#pragma unroll
    for (int h = 0; h < 4; h++) {
#pragma unroll
        for (int off = 1; off <= 2; off <<= 1) {
            ps0[h] += __shfl_xor_sync(0xffffffffu, ps0[h], off);
            pd0[h] += __shfl_xor_sync(0xffffffffu, pd0[h], off);
            ps1[h] += __shfl_xor_sync(0xffffffffu, ps1[h], off);
            pd1[h] += __shfl_xor_sync(0xffffffffu, pd1[h], off);
        }
    }
    if (tig == 0) {
#pragma unroll
        for (int h = 0; h < 4; h++) {
            // pre-scaled by log2(e) so aggregate uses exp2f (single MUFU)
            if (r0 < n) { g_asrc[r0 * 4 + h] = ps0[h] * LOG2E; g_adst[r0 * 4 + h] = pd0[h] * LOG2E; }
            if (r1 < n) { g_asrc[r1 * 4 + h] = ps1[h] * LOG2E; g_adst[r1 * 4 + h] = pd1[h] * LOG2E; }
        }
    }
}

// ---------------- single-pass bucket scatter ---------------------------------
__global__ void scatter_kernel(const int* __restrict__ w, int e, int n) {
    int i = blockIdx.x * blockDim.x + threadIdx.x;
    if (i < e) {
        int is64 = g_is64;
        int s = is64 ? w[2 * (size_t)i]       : w[i];
        int d = is64 ? w[2 * (size_t)(e + i)] : w[(size_t)e + i];
        if ((unsigned)s < (unsigned)n && (unsigned)d < (unsigned)n) {
            int pos = atomicAdd(&g_cursor[d], 1);
            if (pos < BCAP) {
                g_bucket[(size_t)d * BCAP + pos] = s;
            } else {
                int oi = atomicAdd(&g_ovfcnt, 1);
                if (oi < OVFCAP) g_ovf[oi] = make_int2(d, s);
            }
        }
    }
}

// ---------------- aggregation: 2 nodes per warp, 16 lanes each --------------
// lane owns 8 cols (one uint4 of fp16). Scalar work (logit/exp/addressing)
// issues once per warp per 2 edges. Predicated max-count loop avoids
// half-warp divergence.
__device__ __forceinline__ void fma8(float* acc, float p, uint4 u) {
    const __half2* h = (const __half2*)&u;
#pragma unroll
    for (int k = 0; k < 4; k++) {
        float2 f = __half22float2(h[k]);
        acc[2 * k]     = fmaf(p, f.x, acc[2 * k]);
        acc[2 * k + 1] = fmaf(p, f.y, acc[2 * k + 1]);
    }
}

__global__ __launch_bounds__(256) void aggregate_kernel(
    const float4* __restrict__ gat_bias4, float4* __restrict__ out4, int n)
{
    __shared__ float rsum[8][136];
    __shared__ float rsq[8][136];
    const int t = threadIdx.x;
    const int lane = t & 31;
    const int wid = t >> 5;
    const int half = lane >> 4;
    const int hl = lane & 15;
    const int node = blockIdx.x * 16 + wid * 2 + half;
    const int head = hl >> 2;
    const bool valid = node < n;
    const int anode = valid ? node : 0;          // safe address substitute
    const uint4* hh4 = (const uint4*)g_hh;       // 16 uint4 per node row

    float acc[8];
#pragma unroll
    for (int j = 0; j < 8; j++) acc[j] = 0.f;
    float sa = 0.f, sb = 0.f;
    float ad = 0.f;
    int cnt = 0, deg = 0;

    if (valid) {
        deg = g_cursor[node];
        cnt = deg < BCAP ? deg : BCAP;
        ad = g_adst[node * 4 + head];
        float e0 = g_asrc[node * 4 + head] + ad;
        e0 = fmaxf(e0, 0.2f * e0);               // LeakyReLU
        float p0 = exp2f(e0);
        sa = p0;
        fma8(acc, p0, hh4[(size_t)node * 16 + hl]);
    }

    // loop to the max count across the two halves (no divergence)
    int cntmax = cnt;
    {
        int other = __shfl_xor_sync(0xffffffffu, cnt, 16);
        cntmax = cntmax > other ? cntmax : other;
    }
    const int* bp = &g_bucket[(size_t)anode * BCAP];
    int i = 0;
    for (; i + 2 <= cntmax; i += 2) {
        bool on0 = i < cnt, on1 = (i + 1) < cnt;
        int s0 = on0 ? bp[i] : anode;
        int s1 = on1 ? bp[i + 1] : anode;
        float ea = g_asrc[s0 * 4 + head] + ad;
        float eb = g_asrc[s1 * 4 + head] + ad;
        uint4 u0 = hh4[(size_t)s0 * 16 + hl];
        uint4 u1 = hh4[(size_t)s1 * 16 + hl];
        ea = fmaxf(ea, 0.2f * ea);
        eb = fmaxf(eb, 0.2f * eb);
        float pa = on0 ? exp2f(ea) : 0.f;
        float pb = on1 ? exp2f(eb) : 0.f;
        sa += pa; sb += pb;
        fma8(acc, pa, u0);
        fma8(acc, pb, u1);
    }
    if (i < cntmax) {
        bool on0 = i < cnt;
        int s0 = on0 ? bp[i] : anode;
        float ea = g_asrc[s0 * 4 + head] + ad;
        uint4 u0 = hh4[(size_t)s0 * 16 + hl];
        ea = fmaxf(ea, 0.2f * ea);
        float pa = on0 ? exp2f(ea) : 0.f;
        sa += pa;
        fma8(acc, pa, u0);
    }
    // overflow edges (deg > BCAP): ~never taken
    if (__any_sync(0xffffffffu, deg > BCAP)) {
        int oc = g_ovfcnt;
        oc = oc < OVFCAP ? oc : OVFCAP;
        for (int k = 0; k < oc; k++) {
            int2 p = g_ovf[k];
            if (valid && p.x == node) {
                int s0 = p.y;
                float ea = g_asrc[s0 * 4 + head] + ad;
                uint4 u0 = hh4[(size_t)s0 * 16 + hl];
                ea = fmaxf(ea, 0.2f * ea);
                float pa = exp2f(ea);
                sa += pa;
                fma8(acc, pa, u0);
            }
        }
    }

    float o[8];
    if (valid) {
        float inv = 1.0f / (sa + sb);
        float4 b0 = gat_bias4[hl * 2];
        float4 b1 = gat_bias4[hl * 2 + 1];
        o[0] = acc[0] * inv + b0.x;
        o[1] = acc[1] * inv + b0.y;
        o[2] = acc[2] * inv + b0.z;
        o[3] = acc[3] * inv + b0.w;
        o[4] = acc[4] * inv + b1.x;
        o[5] = acc[5] * inv + b1.y;
        o[6] = acc[6] * inv + b1.z;
        o[7] = acc[7] * inv + b1.w;
        out4[(size_t)node * 32 + hl * 2]     = make_float4(o[0], o[1], o[2], o[3]);
        out4[(size_t)node * 32 + hl * 2 + 1] = make_float4(o[4], o[5], o[6], o[7]);
    } else {
#pragma unroll
        for (int j = 0; j < 8; j++) o[j] = 0.f;
    }

    // BN staging: half 0 stores, half 1 accumulates (warp-synchronous)
    if (half == 0) {
#pragma unroll
        for (int j = 0; j < 8; j++) {
            rsum[wid][hl * 8 + j] = o[j];
            rsq[wid][hl * 8 + j] = o[j] * o[j];
        }
    }
    __syncwarp();
    if (half == 1) {
#pragma unroll
        for (int j = 0; j < 8; j++) {
            rsum[wid][hl * 8 + j] += o[j];
            rsq[wid][hl * 8 + j] += o[j] * o[j];
        }
    }
    __syncthreads();
    if (t < 128) {
        float s = 0.f, q = 0.f;
#pragma unroll
        for (int w = 0; w < 8; w++) { s += rsum[w][t]; q += rsq[w][t]; }
        atomicAdd(&g_colsum[t], s);
        atomicAdd(&g_colsq[t], q);
    }
}

// ---------------- final: BN stats + normalize + residual + ReLU -------------
__global__ __launch_bounds__(256) void final_kernel(
    const float4* __restrict__ x4, const float* __restrict__ gamma,
    const float* __restrict__ beta, float4* __restrict__ out4, int n)
{
    __shared__ float ssc[128];
    __shared__ float ssh[128];
    const int t = threadIdx.x;
    if (t < 128) {
        float invn = 1.0f / (float)n;
        float mean = g_colsum[t] * invn;
        float var = g_colsq[t] * invn - mean * mean;
        float sc = gamma[t] * rsqrtf(var + 1e-5f);
        ssc[t] = sc;
        ssh[t] = beta[t] - mean * sc;
    }
    __syncthreads();

    int i = blockIdx.x * blockDim.x + t;
    int total4 = n * 32;
    if (i < total4) {
        int c = (i & 31) * 4;
        float4 sc = *(const float4*)&ssc[c];
        float4 sh = *(const float4*)&ssh[c];
        float4 o = out4[i];
        float4 xv = x4[i];
        o.x = fmaxf(fmaf(sc.x, o.x, sh.x) + xv.x, 0.f);
        o.y = fmaxf(fmaf(sc.y, o.y, sh.y) + xv.y, 0.f);
        o.z = fmaxf(fmaf(sc.z, o.z, sh.z) + xv.z, 0.f);
        o.w = fmaxf(fmaf(sc.w, o.w, sh.w) + xv.w, 0.f);
        out4[i] = o;
    }
}

// ---------------- launch ----------------------------------------------------
extern "C" void kernel_launch(void* const* d_in, const int* in_sizes, int n_in,
                              void* d_out, int out_size)
{
    const float4* x4        = (const float4*)d_in[0];
    const int*    ew        = (const int*)d_in[1];    // edge words (int32 view)
    const float*  W         = (const float*)d_in[2];
    const float*  att_src   = (const float*)d_in[3];
    const float*  att_dst   = (const float*)d_in[4];
    const float4* gat_bias4 = (const float4*)d_in[5];
    const float*  bn_gamma  = (const float*)d_in[6];
    const float*  bn_beta   = (const float*)d_in[7];
    float4* out4 = (float4*)d_out;

    const int n = in_sizes[0] / 128;
    const int e = in_sizes[1] / 2;

    static cudaStream_t s1 = nullptr;
    static cudaEvent_t evFork = nullptr, evJoin = nullptr;
    if (s1 == nullptr) {
        cudaStreamCreateWithFlags(&s1, cudaStreamNonBlocking);
        cudaEventCreateWithFlags(&evFork, cudaEventDisableTiming);
        cudaEventCreateWithFlags(&evJoin, cudaEventDisableTiming);
        cudaFuncSetAttribute(gemm_mma_kernel,
                             cudaFuncAttributeMaxDynamicSharedMemorySize, GEMM_SMEM);
    }

    init_kernel<<<(n + 255) / 256, 256>>>(ew, n);
    cudaEventRecord(evFork, 0);
    cudaStreamWaitEvent(s1, evFork, 0);

    // branch B: single-pass bucket scatter on s1
    scatter_kernel<<<(e + 255) / 256, 256, 0, s1>>>(ew, e, n);
    cudaEventRecord(evJoin, s1);

    // branch A: tensor-core GEMM on default stream (concurrent with branch B)
    gemm_mma_kernel<<<(n + 127) / 128, 256, GEMM_SMEM>>>(x4, W, att_src, att_dst, n);

    // join
    cudaStreamWaitEvent(0, evJoin, 0);
    aggregate_kernel<<<(n + 15) / 16, 256>>>(gat_bias4, out4, n);
    final_kernel<<<(n * 32 + 255) / 256, 256>>>(x4, bn_gamma, bn_beta, out4, n);
}

// round 15
// speedup vs baseline: 1.0931x; 1.0931x over previous
#include <cuda_runtime.h>
#include <cuda_bf16.h>
#include <cuda_fp16.h>
#include <cstdint>

#define NMAX 100000
#define EMAX 1600000
#define BCAP 64                 // fixed bucket capacity per node
#define OVFCAP 32768            // overflow edges (deg > BCAP), ~never used

typedef unsigned long long ull;

// ---------------- device scratch (static: no runtime allocation) ------------
// Invariant: g_cursor/g_ovfcnt/g_colsum/g_colsq are zero at kernel_launch entry
// (zero at module load; restored by final_kernel / scatter_kernel each call).
__device__ __half2 g_hh[(size_t)NMAX * 64];   // x @ W   [N,128] as half2[N,64]
__device__ float   g_asrc[NMAX * 4];          // per-node att logits * log2(e)
__device__ float   g_adst[NMAX * 4];          // per-node att logits * log2(e)
__device__ int     g_cursor[NMAX];            // per-node degree counter
__device__ int     g_bucket[(size_t)NMAX * BCAP];  // src ids, fixed slots per dst
__device__ int2    g_ovf[OVFCAP];             // (dst, src) overflow edges
__device__ int     g_ovfcnt;
__device__ float   g_colsum[128];
__device__ float   g_colsq[128];
__device__ __nv_bfloat16 g_wthi[128 * 128];   // W^T hi  [nn][k]
__device__ __nv_bfloat16 g_wtlo[128 * 128];   // W^T lo  [nn][k]

// ---------------- prepW: one-time W transpose + bf16 hi/lo split ------------
__global__ void prepw_kernel(const float* __restrict__ W) {
    int idx = blockIdx.x * blockDim.x + threadIdx.x;   // 16384 threads
    int k = idx >> 7, nn = idx & 127;
    float w = W[idx];                                   // coalesced read
    __nv_bfloat16 hi = __float2bfloat16(w);
    __nv_bfloat16 lo = __float2bfloat16(w - __bfloat162float(hi));
    g_wthi[nn * 128 + k] = hi;
    g_wtlo[nn * 128 + k] = lo;
}

// ---------------- GEMM via mma.sync bf16 2-term split, fused logits ---------
#define MMA_BF16(d, a0, a1, a2, a3, b0, b1) \
    asm volatile("mma.sync.aligned.m16n8k16.row.col.f32.bf16.bf16.f32 " \
        "{%0,%1,%2,%3}, {%4,%5,%6,%7}, {%8,%9}, {%0,%1,%2,%3};" \
        : "+f"((d)[0]), "+f"((d)[1]), "+f"((d)[2]), "+f"((d)[3]) \
        : "r"(a0), "r"(a1), "r"(a2), "r"(a3), "r"(b0), "r"(b1))

static constexpr int AST = 136;                       // bf16 row stride (conflict-free)
static constexpr int SZ_TILE = 128 * AST * 2;         // 34816 B per bf16 tile
static constexpr int SM_AHI = 0;
static constexpr int SM_ALO = SM_AHI + SZ_TILE;
static constexpr int SM_BHI = SM_ALO + SZ_TILE;       // Wt [n][k]
static constexpr int SM_BLO = SM_BHI + SZ_TILE;
static constexpr int SM_ATT = SM_BLO + SZ_TILE;       // 256 floats (src|dst)
static constexpr int GEMM_SMEM = SM_ATT + 1024;       // 140288 B
static constexpr float LOG2E = 1.4426950408889634f;

__global__ __launch_bounds__(256, 1) void gemm_mma_kernel(
    const float4* __restrict__ x4,
    const float* __restrict__ att_src, const float* __restrict__ att_dst,
    int n)
{
    extern __shared__ char smem[];
    __nv_bfloat16* sAhi = (__nv_bfloat16*)(smem + SM_AHI);
    __nv_bfloat16* sAlo = (__nv_bfloat16*)(smem + SM_ALO);
    __nv_bfloat16* sBhi = (__nv_bfloat16*)(smem + SM_BHI);
    __nv_bfloat16* sBlo = (__nv_bfloat16*)(smem + SM_BLO);
    float* s_att = (float*)(smem + SM_ATT);           // [0:128) src, [128:256) dst

    const int tid = threadIdx.x;
    const int row0 = blockIdx.x * 128;

    if (tid < 128) { s_att[tid] = att_src[tid]; s_att[128 + tid] = att_dst[tid]; }

    // B fill from precomputed Wt hi/lo: 16 uint4 LDG + 16 STS.128 per thread
    {
        const uint4* whi4 = (const uint4*)g_wthi;
        const uint4* wlo4 = (const uint4*)g_wtlo;
#pragma unroll
        for (int i = tid; i < 2048; i += 256) {       // i = 8-elem group
            int nn = i >> 4, k8 = (i & 15) * 8;
            uint32_t off = nn * (AST * 2) + k8 * 2;   // byte offset (16B aligned)
            *(uint4*)(smem + SM_BHI + off) = whi4[i];
            *(uint4*)(smem + SM_BLO + off) = wlo4[i];
        }
    }
    for (int i = tid; i < 128 * 32; i += 256) {
        int r = i >> 5, q = i & 31;
        int grow = row0 + r;
        float4 v = make_float4(0.f, 0.f, 0.f, 0.f);
        if (grow < n) v = x4[(size_t)grow * 32 + q];
        __nv_bfloat162 h0 = __floats2bfloat162_rn(v.x, v.y);
        __nv_bfloat162 h1 = __floats2bfloat162_rn(v.z, v.w);
        __nv_bfloat162 l0 = __floats2bfloat162_rn(v.x - __bfloat162float(h0.x),
                                                  v.y - __bfloat162float(h0.y));
        __nv_bfloat162 l1 = __floats2bfloat162_rn(v.z - __bfloat162float(h1.x),
                                                  v.w - __bfloat162float(h1.y));
        uint32_t base = r * AST + q * 4;
        *(uint32_t*)&sAhi[base]     = *(uint32_t*)&h0;
        *(uint32_t*)&sAhi[base + 2] = *(uint32_t*)&h1;
        *(uint32_t*)&sAlo[base]     = *(uint32_t*)&l0;
        *(uint32_t*)&sAlo[base + 2] = *(uint32_t*)&l1;
    }
    __syncthreads();

    const int lane = tid & 31, warp = tid >> 5;
    const int g = lane >> 2, tig = lane & 3;
    const int mrow = warp * 16;

    float d[16][4];
#pragma unroll
    for (int nt = 0; nt < 16; nt++)
#pragma unroll
        for (int j = 0; j < 4; j++) d[nt][j] = 0.f;

#pragma unroll
    for (int term = 0; term < 3; term++) {
        const __nv_bfloat16* A = (term == 2) ? sAlo : sAhi;
        const __nv_bfloat16* B = (term == 1) ? sBlo : sBhi;
#pragma unroll
        for (int k0 = 0; k0 < 128; k0 += 16) {
            int kc = k0 + tig * 2;
            uint32_t a0 = *(const uint32_t*)&A[(mrow + g) * AST + kc];
            uint32_t a1 = *(const uint32_t*)&A[(mrow + g + 8) * AST + kc];
            uint32_t a2 = *(const uint32_t*)&A[(mrow + g) * AST + kc + 8];
            uint32_t a3 = *(const uint32_t*)&A[(mrow + g + 8) * AST + kc + 8];
#pragma unroll
            for (int nt = 0; nt < 16; nt++) {
                uint32_t b0 = *(const uint32_t*)&B[(nt * 8 + g) * AST + kc];
                uint32_t b1 = *(const uint32_t*)&B[(nt * 8 + g) * AST + kc + 8];
                MMA_BF16(d[nt], a0, a1, a2, a3, b0, b1);
            }
        }
    }

    const int r0 = row0 + mrow + g;
    const int r1 = r0 + 8;
    float ps0[4], pd0[4], ps1[4], pd1[4];
#pragma unroll
    for (int h = 0; h < 4; h++) { ps0[h] = pd0[h] = ps1[h] = pd1[h] = 0.f; }
#pragma unroll
    for (int nt = 0; nt < 16; nt++) {
        int c0 = nt * 8 + tig * 2;
        int h = nt >> 2;
        float a_s0 = s_att[c0], a_s1 = s_att[c0 + 1];
        float a_d0 = s_att[128 + c0], a_d1 = s_att[128 + c0 + 1];
        ps0[h] += d[nt][0] * a_s0 + d[nt][1] * a_s1;
        pd0[h] += d[nt][0] * a_d0 + d[nt][1] * a_d1;
        ps1[h] += d[nt][2] * a_s0 + d[nt][3] * a_s1;
        pd1[h] += d[nt][2] * a_d0 + d[nt][3] * a_d1;
        if (r0 < n) g_hh[(size_t)r0 * 64 + (c0 >> 1)] = __floats2half2_rn(d[nt][0], d[nt][1]);
        if (r1 < n) g_hh[(size_t)r1 * 64 + (c0 >> 1)] = __floats2half2_rn(d[nt][2], d[nt][3]);
    }
#pragma unroll
    for (int h = 0; h < 4; h++) {
#pragma unroll
        for (int off = 1; off <= 2; off <<= 1) {
            ps0[h] += __shfl_xor_sync(0xffffffffu, ps0[h], off);
            pd0[h] += __shfl_xor_sync(0xffffffffu, pd0[h], off);
            ps1[h] += __shfl_xor_sync(0xffffffffu, ps1[h], off);
            pd1[h] += __shfl_xor_sync(0xffffffffu, pd1[h], off);
        }
    }
    if (tig == 0) {
#pragma unroll
        for (int h = 0; h < 4; h++) {
            // pre-scaled by log2(e) so aggregate uses exp2f (single MUFU)
            if (r0 < n) { g_asrc[r0 * 4 + h] = ps0[h] * LOG2E; g_adst[r0 * 4 + h] = pd0[h] * LOG2E; }
            if (r1 < n) { g_asrc[r1 * 4 + h] = ps1[h] * LOG2E; g_adst[r1 * 4 + h] = pd1[h] * LOG2E; }
        }
    }
}

// ---------------- single-pass bucket scatter (+stats zero, +dtype detect) ---
__global__ void scatter_kernel(const int* __restrict__ w, int e, int n) {
    __shared__ int s_is64;
    const int t = threadIdx.x;
    if (t == 0) {
        int all0 = 1;
        for (int j = 1; j < 64; j += 2) all0 &= (w[j] == 0);
        s_is64 = all0;
    }
    if (blockIdx.x == 0 && t < 128) { g_colsum[t] = 0.f; g_colsq[t] = 0.f; }
    __syncthreads();
    const int is64 = s_is64;

    int i = blockIdx.x * blockDim.x + t;
    if (i < e) {
        int s = is64 ? w[2 * (size_t)i]       : w[i];
        int d = is64 ? w[2 * (size_t)(e + i)] : w[(size_t)e + i];
        if ((unsigned)s < (unsigned)n && (unsigned)d < (unsigned)n) {
            int pos = atomicAdd(&g_cursor[d], 1);
            if (pos < BCAP) {
                g_bucket[(size_t)d * BCAP + pos] = s;
            } else {
                int oi = atomicAdd(&g_ovfcnt, 1);
                if (oi < OVFCAP) g_ovf[oi] = make_int2(d, s);
            }
        }
    }
}

// ---------------- warp-per-node softmax aggregation (fp16 h gather) ---------
__global__ __launch_bounds__(256) void aggregate_kernel(
    const float4* __restrict__ gat_bias4, float4* __restrict__ out4, int n)
{
    __shared__ float rsum[8][132];
    __shared__ float rsq[8][132];
    const int t = threadIdx.x;
    const int lane = t & 31;
    const int wid = t >> 5;
    const int node = blockIdx.x * 8 + wid;

    float4 o = make_float4(0.f, 0.f, 0.f, 0.f);
    float4 osq = make_float4(0.f, 0.f, 0.f, 0.f);

    if (node < n) {
        const int head = lane >> 3;
        const float ad = g_adst[node * 4 + head];
        float e0 = g_asrc[node * 4 + head] + ad;
        e0 = e0 > 0.f ? e0 : 0.2f * e0;
        float p0 = exp2f(e0);
        float sa = p0, sb = 0.f;
        const __half2* hh = g_hh;
        __half2 v0 = hh[(size_t)node * 64 + lane * 2];
        __half2 v1 = hh[(size_t)node * 64 + lane * 2 + 1];
        float2 f0 = __half22float2(v0), f1 = __half22float2(v1);
        float4 acc = make_float4(p0 * f0.x, p0 * f0.y, p0 * f1.x, p0 * f1.y);

        const int deg = g_cursor[node];
        const int cnt = deg < BCAP ? deg : BCAP;
        const int4* bp = (const int4*)&g_bucket[(size_t)node * BCAP];
        int i = 0;
        for (; i + 4 <= cnt; i += 4) {
            int4 sv = bp[i >> 2];                 // uniform 16B broadcast
            float ea = g_asrc[sv.x * 4 + head] + ad;
            float eb = g_asrc[sv.y * 4 + head] + ad;
            float ec = g_asrc[sv.z * 4 + head] + ad;
            float ed = g_asrc[sv.w * 4 + head] + ad;
            uint2 ua = *(const uint2*)&hh[(size_t)sv.x * 64 + lane * 2];
            uint2 ub = *(const uint2*)&hh[(size_t)sv.y * 64 + lane * 2];
            uint2 uc = *(const uint2*)&hh[(size_t)sv.z * 64 + lane * 2];
            uint2 ud = *(const uint2*)&hh[(size_t)sv.w * 64 + lane * 2];
            ea = ea > 0.f ? ea : 0.2f * ea;
            eb = eb > 0.f ? eb : 0.2f * eb;
            ec = ec > 0.f ? ec : 0.2f * ec;
            ed = ed > 0.f ? ed : 0.2f * ed;
            float pa = exp2f(ea);
            float pb = exp2f(eb);
            float pc = exp2f(ec);
            float pd = exp2f(ed);
            sa += pa + pc;  sb += pb + pd;
            float2 a0 = __half22float2(*(__half2*)&ua.x), a1 = __half22float2(*(__half2*)&ua.y);
            float2 b0 = __half22float2(*(__half2*)&ub.x), b1 = __half22float2(*(__half2*)&ub.y);
            float2 c0 = __half22float2(*(__half2*)&uc.x), c1 = __half22float2(*(__half2*)&uc.y);
            float2 d0 = __half22float2(*(__half2*)&ud.x), d1 = __half22float2(*(__half2*)&ud.y);
            acc.x = fmaf(pa, a0.x, acc.x);
            acc.y = fmaf(pa, a0.y, acc.y);
            acc.z = fmaf(pa, a1.x, acc.z);
            acc.w = fmaf(pa, a1.y, acc.w);
            acc.x = fmaf(pb, b0.x, acc.x);
            acc.y = fmaf(pb, b0.y, acc.y);
            acc.z = fmaf(pb, b1.x, acc.z);
            acc.w = fmaf(pb, b1.y, acc.w);
            acc.x = fmaf(pc, c0.x, acc.x);
            acc.y = fmaf(pc, c0.y, acc.y);
            acc.z = fmaf(pc, c1.x, acc.z);
            acc.w = fmaf(pc, c1.y, acc.w);
            acc.x = fmaf(pd, d0.x, acc.x);
            acc.y = fmaf(pd, d0.y, acc.y);
            acc.z = fmaf(pd, d1.x, acc.z);
            acc.w = fmaf(pd, d1.y, acc.w);
        }
        for (; i < cnt; i++) {
            int s0 = g_bucket[(size_t)node * BCAP + i];
            float ea = g_asrc[s0 * 4 + head] + ad;
            uint2 ua = *(const uint2*)&hh[(size_t)s0 * 64 + lane * 2];
            ea = ea > 0.f ? ea : 0.2f * ea;
            float pa = exp2f(ea);
            sa += pa;
            float2 a0 = __half22float2(*(__half2*)&ua.x), a1 = __half22float2(*(__half2*)&ua.y);
            acc.x = fmaf(pa, a0.x, acc.x);
            acc.y = fmaf(pa, a0.y, acc.y);
            acc.z = fmaf(pa, a1.x, acc.z);
            acc.w = fmaf(pa, a1.y, acc.w);
        }
        // overflow edges (deg > BCAP): ~never taken
        if (deg > BCAP) {
            int oc = g_ovfcnt;
            oc = oc < OVFCAP ? oc : OVFCAP;
            for (int k = 0; k < oc; k++) {
                int2 p = g_ovf[k];
                if (p.x == node) {
                    int s0 = p.y;
                    float ea = g_asrc[s0 * 4 + head] + ad;
                    uint2 ua = *(const uint2*)&hh[(size_t)s0 * 64 + lane * 2];
                    ea = ea > 0.f ? ea : 0.2f * ea;
                    float pa = exp2f(ea);
                    sa += pa;
                    float2 a0 = __half22float2(*(__half2*)&ua.x);
                    float2 a1 = __half22float2(*(__half2*)&ua.y);
                    acc.x = fmaf(pa, a0.x, acc.x);
                    acc.y = fmaf(pa, a0.y, acc.y);
                    acc.z = fmaf(pa, a1.x, acc.z);
                    acc.w = fmaf(pa, a1.y, acc.w);
                }
            }
        }
        float inv = 1.0f / (sa + sb);
        float4 b = gat_bias4[lane];
        o.x = acc.x * inv + b.x;
        o.y = acc.y * inv + b.y;
        o.z = acc.z * inv + b.z;
        o.w = acc.w * inv + b.w;
        out4[(size_t)node * 32 + lane] = o;
        osq = make_float4(o.x * o.x, o.y * o.y, o.z * o.z, o.w * o.w);
    }

    // conflict-free staged BN reduction
    *(float4*)&rsum[wid][lane * 4] = o;
    *(float4*)&rsq[wid][lane * 4]  = osq;
    __syncthreads();
    if (t < 128) {
        float s = 0.f, q = 0.f;
#pragma unroll
        for (int w = 0; w < 8; w++) { s += rsum[w][t]; q += rsq[w][t]; }
        atomicAdd(&g_colsum[t], s);
        atomicAdd(&g_colsq[t], q);
    }
}

// ---------------- final: BN stats + normalize + residual + ReLU -------------
// Also restores the zero-invariant on g_cursor / g_ovfcnt for the next call.
__global__ __launch_bounds__(256) void final_kernel(
    const float4* __restrict__ x4, const float* __restrict__ gamma,
    const float* __restrict__ beta, float4* __restrict__ out4, int n)
{
    __shared__ float ssc[128];
    __shared__ float ssh[128];
    const int t = threadIdx.x;
    if (t < 128) {
        float invn = 1.0f / (float)n;
        float mean = g_colsum[t] * invn;
        float var = g_colsq[t] * invn - mean * mean;
        float sc = gamma[t] * rsqrtf(var + 1e-5f);
        ssc[t] = sc;
        ssh[t] = beta[t] - mean * sc;
    }
    __syncthreads();

    int i = blockIdx.x * blockDim.x + t;
    if (i == 0) g_ovfcnt = 0;
    if (i < n) g_cursor[i] = 0;          // restore zero-invariant
    int total4 = n * 32;
    if (i < total4) {
        int c = (i & 31) * 4;
        float4 sc = *(const float4*)&ssc[c];
        float4 sh = *(const float4*)&ssh[c];
        float4 o = out4[i];
        float4 xv = x4[i];
        o.x = fmaxf(fmaf(sc.x, o.x, sh.x) + xv.x, 0.f);
        o.y = fmaxf(fmaf(sc.y, o.y, sh.y) + xv.y, 0.f);
        o.z = fmaxf(fmaf(sc.z, o.z, sh.z) + xv.z, 0.f);
        o.w = fmaxf(fmaf(sc.w, o.w, sh.w) + xv.w, 0.f);
        out4[i] = o;
    }
}

// ---------------- launch ----------------------------------------------------
extern "C" void kernel_launch(void* const* d_in, const int* in_sizes, int n_in,
                              void* d_out, int out_size)
{
    const float4* x4        = (const float4*)d_in[0];
    const int*    ew        = (const int*)d_in[1];    // edge words (int32 view)
    const float*  W         = (const float*)d_in[2];
    const float*  att_src   = (const float*)d_in[3];
    const float*  att_dst   = (const float*)d_in[4];
    const float4* gat_bias4 = (const float4*)d_in[5];
    const float*  bn_gamma  = (const float*)d_in[6];
    const float*  bn_beta   = (const float*)d_in[7];
    float4* out4 = (float4*)d_out;

    const int n = in_sizes[0] / 128;
    const int e = in_sizes[1] / 2;

    static cudaStream_t s1 = nullptr;
    static cudaEvent_t evFork = nullptr, evJoin = nullptr;
    if (s1 == nullptr) {
        cudaStreamCreateWithFlags(&s1, cudaStreamNonBlocking);
        cudaEventCreateWithFlags(&evFork, cudaEventDisableTiming);
        cudaEventCreateWithFlags(&evJoin, cudaEventDisableTiming);
        cudaFuncSetAttribute(gemm_mma_kernel,
                             cudaFuncAttributeMaxDynamicSharedMemorySize, GEMM_SMEM);
    }

    cudaEventRecord(evFork, 0);
    cudaStreamWaitEvent(s1, evFork, 0);

    // branch B: single-pass bucket scatter on s1 (cursor pre-zeroed invariant)
    scatter_kernel<<<(e + 255) / 256, 256, 0, s1>>>(ew, e, n);
    cudaEventRecord(evJoin, s1);

    // branch A: W prep + tensor-core GEMM on default stream
    prepw_kernel<<<64, 256>>>(W);
    gemm_mma_kernel<<<(n + 127) / 128, 256, GEMM_SMEM>>>(x4, att_src, att_dst, n);

    // join
    cudaStreamWaitEvent(0, evJoin, 0);
    aggregate_kernel<<<(n + 7) / 8, 256>>>(gat_bias4, out4, n);
    final_kernel<<<(n * 32 + 255) / 256, 256>>>(x4, bn_gamma, bn_beta, out4, n);
}